// round 1
// baseline (speedup 1.0000x reference)
#include <cuda_runtime.h>
#include <cuda_bf16.h>
#include <math.h>

// Problem constants
#define BATCH 8
#define NTOK  1024
#define DMODEL 512
#define HEADS 8
#define DHEAD 64
#define CHh 6
#define CDd 64
#define IDIM 512          // HEADS*DHEAD
#define TOKENS (BATCH*NTOK)   // 8192
#define CKDIM (CHh*CDd)       // 384

// ---------------- scratch (device globals; no allocation allowed) -------------
__device__ float g_qkv [TOKENS * 3 * IDIM];   // (8192, 1536)
__device__ float g_ckx [TOKENS * CKDIM];      // (8192, 384) normalized rearranged
__device__ float g_ta  [TOKENS * IDIM];
__device__ float g_tb  [TOKENS * IDIM];
__device__ float g_ckh [TOKENS * IDIM];
__device__ float g_cvh [TOKENS * IDIM];
__device__ float g_out [TOKENS * IDIM];       // self-attn out, token-major
__device__ float g_outc[TOKENS * IDIM];       // context-attn out, token-major
__device__ float g_mlp [TOKENS * IDIM];
__device__ float g_comb[TOKENS * IDIM];

// ---------------- GEMM: C = act(A @ B^T + bias) --------------------------------
// A: (M,K) row-major, B: (N,K) row-major, C: (M,N) row-major.
// BM=BN=128, BK=16, 256 threads, 8x8 per thread (split-tile mapping).
#define BM 128
#define BN 128
#define BK 16

template<int ACT>
__global__ __launch_bounds__(256) void gemm_kernel(
    const float* __restrict__ A, const float* __restrict__ B,
    const float* __restrict__ bias, float* __restrict__ C,
    int M, int N, int K)
{
    __shared__ float As[BK][BM];
    __shared__ float Bs[BK][BN];
    const int tid = threadIdx.x;
    const int tx = tid & 15, ty = tid >> 4;
    const int bx = blockIdx.x, by = blockIdx.y;
    const float* Ab = A + (size_t)by * BM * K;
    const float* Bb = B + (size_t)bx * BN * K;

    float acc[8][8];
#pragma unroll
    for (int i = 0; i < 8; i++)
#pragma unroll
        for (int j = 0; j < 8; j++) acc[i][j] = 0.0f;

    const int ktiles = K / BK;
    for (int kt = 0; kt < ktiles; kt++) {
#pragma unroll
        for (int l = 0; l < 2; l++) {
            int f = tid + l * 256;
            int row = f >> 2, kq = f & 3;
            float4 va = *(const float4*)(Ab + (size_t)row * K + kt * BK + kq * 4);
            As[kq*4+0][row] = va.x; As[kq*4+1][row] = va.y;
            As[kq*4+2][row] = va.z; As[kq*4+3][row] = va.w;
            float4 vb = *(const float4*)(Bb + (size_t)row * K + kt * BK + kq * 4);
            Bs[kq*4+0][row] = vb.x; Bs[kq*4+1][row] = vb.y;
            Bs[kq*4+2][row] = vb.z; Bs[kq*4+3][row] = vb.w;
        }
        __syncthreads();
#pragma unroll
        for (int kk = 0; kk < BK; kk++) {
            float4 a0 = *(const float4*)&As[kk][ty * 4];
            float4 a1 = *(const float4*)&As[kk][64 + ty * 4];
            float4 b0 = *(const float4*)&Bs[kk][tx * 4];
            float4 b1 = *(const float4*)&Bs[kk][64 + tx * 4];
            float a[8] = {a0.x,a0.y,a0.z,a0.w,a1.x,a1.y,a1.z,a1.w};
            float b[8] = {b0.x,b0.y,b0.z,b0.w,b1.x,b1.y,b1.z,b1.w};
#pragma unroll
            for (int i = 0; i < 8; i++)
#pragma unroll
                for (int j = 0; j < 8; j++) acc[i][j] += a[i] * b[j];
        }
        __syncthreads();
    }

    // epilogue
    float bcol[8];
#pragma unroll
    for (int j = 0; j < 8; j++) {
        int col = bx * BN + (j < 4 ? tx * 4 + j : 64 + tx * 4 + (j - 4));
        bcol[j] = bias ? bias[col] : 0.0f;
    }
#pragma unroll
    for (int i = 0; i < 8; i++) {
        int row = by * BM + (i < 4 ? ty * 4 + i : 64 + ty * 4 + (i - 4));
        float v[8];
#pragma unroll
        for (int j = 0; j < 8; j++) {
            float x = acc[i][j] + bcol[j];
            if (ACT == 1) x = x > 0.0f ? x : 0.2f * x;
            else if (ACT == 2) x = 0.5f * x * (1.0f + erff(x * 0.70710678118654752f));
            v[j] = x;
        }
        float4* c0 = (float4*)(C + (size_t)row * N + bx * BN + tx * 4);
        float4* c1 = (float4*)(C + (size_t)row * N + bx * BN + 64 + tx * 4);
        *c0 = make_float4(v[0], v[1], v[2], v[3]);
        *c1 = make_float4(v[4], v[5], v[6], v[7]);
    }
}

// ---------------- Flash attention -------------------------------------------
// grid: (N/64, H, B), 256 threads (8 warps x 8 qrows, 4 lanes per qrow).
// Q read with stride ldq (head offset applied by caller semantics: base already
// points at column 0 of q; kernel adds h*64). Output token-major (ld 512).
__global__ __launch_bounds__(256) void attn_kernel(
    const float* __restrict__ Q, const float* __restrict__ K,
    const float* __restrict__ V, float* __restrict__ O,
    int ldq, int ldkv)
{
    __shared__ float Ks[64][64];
    __shared__ float Vs[64][64];
    __shared__ float Ps[64][64];

    const int b = blockIdx.z, h = blockIdx.y, qt = blockIdx.x;
    const int tid = threadIdx.x;
    const int warp = tid >> 5, lane = tid & 31;
    const int qrow = warp * 8 + (lane >> 2);   // 0..63 within the q tile
    const int kg = lane & 3;                   // dim/key group 0..3

    const float* Qp = Q + ((size_t)b * NTOK + qt * 64) * ldq + h * 64;
    const float* Kp = K + ((size_t)b * NTOK) * ldkv + h * 64;
    const float* Vp = V + ((size_t)b * NTOK) * ldkv + h * 64;

    float qf[16];
#pragma unroll
    for (int j4 = 0; j4 < 4; j4++) {
        float4 v = *(const float4*)(Qp + (size_t)qrow * ldq + kg * 16 + j4 * 4);
        qf[j4*4+0] = v.x; qf[j4*4+1] = v.y; qf[j4*4+2] = v.z; qf[j4*4+3] = v.w;
    }

    float m = -1e30f, l = 0.0f;
    float o[16];
#pragma unroll
    for (int i = 0; i < 16; i++) o[i] = 0.0f;

    for (int kt = 0; kt < NTOK / 64; kt++) {
        __syncthreads();  // all warps done with Ks/Vs/Ps from prev iter
        {
            int r0 = tid >> 4;
            int c = (tid & 15) * 4;
#pragma unroll
            for (int rep = 0; rep < 4; rep++) {
                int r = r0 + rep * 16;
                *(float4*)&Ks[r][c] = *(const float4*)(Kp + (size_t)(kt * 64 + r) * ldkv + c);
                *(float4*)&Vs[r][c] = *(const float4*)(Vp + (size_t)(kt * 64 + r) * ldkv + c);
            }
        }
        __syncthreads();

        // ---- S = q . k over all 64 keys (4-lane partial dots + shfl reduce)
        float s[16];
#pragma unroll
        for (int kc = 0; kc < 4; kc++) {
#pragma unroll
            for (int kk = 0; kk < 16; kk++) {
                int k = kc * 16 + kk;
                float ps = 0.0f;
#pragma unroll
                for (int j = 0; j < 16; j++) ps += qf[j] * Ks[k][kg * 16 + j];
                ps += __shfl_xor_sync(0xffffffffu, ps, 1);
                ps += __shfl_xor_sync(0xffffffffu, ps, 2);
                if (kc == kg) s[kk] = ps * 0.125f;   // DH^-0.5
            }
        }

        // ---- online softmax over this 64-key tile
        float tmax = s[0];
#pragma unroll
        for (int i = 1; i < 16; i++) tmax = fmaxf(tmax, s[i]);
        tmax = fmaxf(tmax, __shfl_xor_sync(0xffffffffu, tmax, 1));
        tmax = fmaxf(tmax, __shfl_xor_sync(0xffffffffu, tmax, 2));
        float mnew = fmaxf(m, tmax);
        float alpha = expf(m - mnew);
        float psum = 0.0f;
#pragma unroll
        for (int i = 0; i < 16; i++) { s[i] = expf(s[i] - mnew); psum += s[i]; }
        psum += __shfl_xor_sync(0xffffffffu, psum, 1);
        psum += __shfl_xor_sync(0xffffffffu, psum, 2);
        l = l * alpha + psum;
        m = mnew;
#pragma unroll
        for (int i = 0; i < 16; i++) o[i] *= alpha;

#pragma unroll
        for (int i = 0; i < 16; i++) Ps[qrow][kg * 16 + i] = s[i];
        __syncwarp();  // Ps rows for this warp's qrows are written by this warp only

        // ---- O += P @ V  (thread now owns dims kg*16..+15 of its qrow)
#pragma unroll
        for (int k = 0; k < 64; k++) {
            float pv = Ps[qrow][k];
            const float* vr = &Vs[k][kg * 16];
#pragma unroll
            for (int i = 0; i < 16; i++) o[i] += pv * vr[i];
        }
    }

    float inv = 1.0f / l;
    float* Op = O + ((size_t)b * NTOK + qt * 64 + qrow) * IDIM + h * 64 + kg * 16;
#pragma unroll
    for (int i4 = 0; i4 < 4; i4++) {
        *(float4*)(Op + i4 * 4) = make_float4(o[i4*4+0]*inv, o[i4*4+1]*inv,
                                              o[i4*4+2]*inv, o[i4*4+3]*inv);
    }
}

// ---------------- Column L2-norm over the token axis ---------------------------
// ck/cv variant: src (b, 6, n, 64) -> dst token-major (8192, 384), each column
// (b, h*64+d) divided by its norm over n. grid (6, 8), 256 threads.
__global__ __launch_bounds__(256) void colnorm_ck_kernel(
    const float* __restrict__ src, float* __restrict__ dst)
{
    const int hh = blockIdx.x, b = blockIdx.y;
    __shared__ float red[256];
    __shared__ float inv[64];
    const int tid = threadIdx.x;
    const int d = tid & 63;
    const int ng = tid >> 6;  // 0..3
    const float* s = src + (((size_t)b * CHh + hh) * NTOK) * CDd;
    float acc = 0.0f;
    for (int n = ng; n < NTOK; n += 4) {
        float v = s[(size_t)n * CDd + d];
        acc += v * v;
    }
    red[tid] = acc;
    __syncthreads();
    if (tid < 64) {
        float t = red[tid] + red[tid+64] + red[tid+128] + red[tid+192];
        inv[tid] = 1.0f / fmaxf(sqrtf(t), 1e-12f);
    }
    __syncthreads();
    float iv = inv[d];
    float* dp = dst + (size_t)b * NTOK * CKDIM + hh * CDd;
    for (int n = ng; n < NTOK; n += 4) {
        dp[(size_t)n * CKDIM + d] = s[(size_t)n * CDd + d] * iv;
    }
}

// token-major variant: src/dst (8192, 512), columns normalized per (b, col).
// grid (8 colgroups, 8 batches), 256 threads.
__global__ __launch_bounds__(256) void colnorm_tok_kernel(
    const float* __restrict__ src, float* __restrict__ dst)
{
    const int hh = blockIdx.x, b = blockIdx.y;
    __shared__ float red[256];
    __shared__ float inv[64];
    const int tid = threadIdx.x;
    const int d = tid & 63;
    const int ng = tid >> 6;
    const float* s = src + (size_t)b * NTOK * IDIM + hh * 64;
    float acc = 0.0f;
    for (int n = ng; n < NTOK; n += 4) {
        float v = s[(size_t)n * IDIM + d];
        acc += v * v;
    }
    red[tid] = acc;
    __syncthreads();
    if (tid < 64) {
        float t = red[tid] + red[tid+64] + red[tid+128] + red[tid+192];
        inv[tid] = 1.0f / fmaxf(sqrtf(t), 1e-12f);
    }
    __syncthreads();
    float iv = inv[d];
    float* dp = dst + (size_t)b * NTOK * IDIM + hh * 64;
    for (int n = ng; n < NTOK; n += 4) {
        dp[(size_t)n * IDIM + d] = s[(size_t)n * IDIM + d] * iv;
    }
}

// ---------------- combine: out - mlp * sub_ratio --------------------------------
__global__ __launch_bounds__(256) void combine_kernel(
    const float* __restrict__ a, const float* __restrict__ mlp,
    const float* __restrict__ ratio, float* __restrict__ dst)
{
    int i = blockIdx.x * blockDim.x + threadIdx.x;
    if (i < TOKENS * IDIM) {
        dst[i] = a[i] - mlp[i] * ratio[i & (IDIM - 1)];
    }
}

// ---------------- launch -----------------------------------------------------
extern "C" void kernel_launch(void* const* d_in, const int* in_sizes, int n_in,
                              void* d_out, int out_size)
{
    const float* x      = (const float*)d_in[0];
    const float* ck     = (const float*)d_in[1];
    const float* cv     = (const float*)d_in[2];
    const float* w_qkv  = (const float*)d_in[3];
    const float* w_out  = (const float*)d_in[4];
    const float* b_out  = (const float*)d_in[5];
    const float* ckw0   = (const float*)d_in[6];
    const float* ckb0   = (const float*)d_in[7];
    const float* ckw1   = (const float*)d_in[8];
    const float* ckb1   = (const float*)d_in[9];
    const float* ckw2   = (const float*)d_in[10];
    const float* ckb2   = (const float*)d_in[11];
    const float* cvw0   = (const float*)d_in[12];
    const float* cvb0   = (const float*)d_in[13];
    const float* cvw1   = (const float*)d_in[14];
    const float* cvb1   = (const float*)d_in[15];
    const float* cvw2   = (const float*)d_in[16];
    const float* cvb2   = (const float*)d_in[17];
    const float* nl_w   = (const float*)d_in[18];
    const float* nl_b   = (const float*)d_in[19];
    const float* ratio  = (const float*)d_in[20];
    float* out = (float*)d_out;

    float *qkv, *ckx, *ta, *tb, *ckh, *cvh, *oself, *octx, *mlp, *comb;
    cudaGetSymbolAddress((void**)&qkv,  g_qkv);
    cudaGetSymbolAddress((void**)&ckx,  g_ckx);
    cudaGetSymbolAddress((void**)&ta,   g_ta);
    cudaGetSymbolAddress((void**)&tb,   g_tb);
    cudaGetSymbolAddress((void**)&ckh,  g_ckh);
    cudaGetSymbolAddress((void**)&cvh,  g_cvh);
    cudaGetSymbolAddress((void**)&oself,g_out);
    cudaGetSymbolAddress((void**)&octx, g_outc);
    cudaGetSymbolAddress((void**)&mlp,  g_mlp);
    cudaGetSymbolAddress((void**)&comb, g_comb);

    dim3 blk(256);

    // 1) qkv = x @ w_qkv^T  (8192x512 @ 512x1536)
    gemm_kernel<0><<<dim3(3 * IDIM / BN, TOKENS / BM), blk>>>(
        x, w_qkv, nullptr, qkv, TOKENS, 3 * IDIM, DMODEL);

    // 2) ck style vectorizer
    colnorm_ck_kernel<<<dim3(CHh, BATCH), blk>>>(ck, ckx);
    gemm_kernel<1><<<dim3(IDIM / BN, TOKENS / BM), blk>>>(ckx, ckw0, ckb0, ta, TOKENS, IDIM, CKDIM);
    gemm_kernel<1><<<dim3(IDIM / BN, TOKENS / BM), blk>>>(ta,  ckw1, ckb1, tb, TOKENS, IDIM, IDIM);
    gemm_kernel<1><<<dim3(IDIM / BN, TOKENS / BM), blk>>>(tb,  ckw2, ckb2, ckh, TOKENS, IDIM, IDIM);

    // 3) cv style vectorizer
    colnorm_ck_kernel<<<dim3(CHh, BATCH), blk>>>(cv, ckx);
    gemm_kernel<1><<<dim3(IDIM / BN, TOKENS / BM), blk>>>(ckx, cvw0, cvb0, ta, TOKENS, IDIM, CKDIM);
    gemm_kernel<1><<<dim3(IDIM / BN, TOKENS / BM), blk>>>(ta,  cvw1, cvb1, tb, TOKENS, IDIM, IDIM);
    gemm_kernel<1><<<dim3(IDIM / BN, TOKENS / BM), blk>>>(tb,  cvw2, cvb2, cvh, TOKENS, IDIM, IDIM);

    // 4) self attention: q|k|v are column blocks of qkv (ld 1536)
    attn_kernel<<<dim3(NTOK / 64, HEADS, BATCH), blk>>>(
        qkv, qkv + IDIM, qkv + 2 * IDIM, oself, 3 * IDIM, 3 * IDIM);

    // 5) context attention: same q, K/V from style vectorizers (ld 512)
    attn_kernel<<<dim3(NTOK / 64, HEADS, BATCH), blk>>>(
        qkv, ckh, cvh, octx, 3 * IDIM, IDIM);

    // 6) MLP block on context output: col-norm then Linear+GELU
    colnorm_tok_kernel<<<dim3(IDIM / 64, BATCH), blk>>>(octx, ta);
    gemm_kernel<2><<<dim3(IDIM / BN, TOKENS / BM), blk>>>(ta, nl_w, nl_b, mlp, TOKENS, IDIM, IDIM);

    // 7) combine: out - mlp * sub_ratio
    combine_kernel<<<(TOKENS * IDIM + 255) / 256, blk>>>(oself, mlp, ratio, comb);

    // 8) final projection -> d_out
    gemm_kernel<0><<<dim3(IDIM / BN, TOKENS / BM), blk>>>(comb, w_out, b_out, out, TOKENS, IDIM, IDIM);
}

// round 3
// speedup vs baseline: 4.5171x; 4.5171x over previous
#include <cuda_runtime.h>
#include <cuda_bf16.h>
#include <math.h>
#include <stdint.h>

// Problem constants
#define BATCH 8
#define NTOK  1024
#define DMODEL 512
#define HEADS 8
#define DHEAD 64
#define CHh 6
#define CDd 64
#define IDIM 512
#define TOKENS (BATCH*NTOK)   // 8192
#define CKDIM (CHh*CDd)       // 384

// ---------------- scratch ----------------------------------------------------
__device__ float g_qkv [TOKENS * 3 * IDIM];
__device__ float g_ckx [TOKENS * CKDIM];
__device__ float g_ta  [TOKENS * IDIM];
__device__ float g_tb  [TOKENS * IDIM];
__device__ float g_ckh [TOKENS * IDIM];
__device__ float g_cvh [TOKENS * IDIM];
__device__ float g_out [TOKENS * IDIM];
__device__ float g_outc[TOKENS * IDIM];
__device__ float g_mlp [TOKENS * IDIM];
__device__ float g_comb[TOKENS * IDIM];

// ---------------- mma helpers ------------------------------------------------
__device__ __forceinline__ void mma_bf16(float c[4],
    uint32_t a0, uint32_t a1, uint32_t a2, uint32_t a3,
    uint32_t b0, uint32_t b1)
{
    asm volatile(
        "mma.sync.aligned.m16n8k16.row.col.f32.bf16.bf16.f32 "
        "{%0,%1,%2,%3}, {%4,%5,%6,%7}, {%8,%9}, {%0,%1,%2,%3};\n"
        : "+f"(c[0]), "+f"(c[1]), "+f"(c[2]), "+f"(c[3])
        : "r"(a0), "r"(a1), "r"(a2), "r"(a3), "r"(b0), "r"(b1));
}

__device__ __forceinline__ uint32_t packbf(float x, float y) {
    __nv_bfloat162 t = __floats2bfloat162_rn(x, y);
    return *(uint32_t*)&t;
}
__device__ __forceinline__ void hilo(float x, float& h, float& l) {
    __nv_bfloat16 hb = __float2bfloat16_rn(x);
    h = __bfloat162float(hb);
    l = x - h;
}

// ---------------- bf16-split GEMM: C = act(A @ B^T + bias) ---------------------
// A: (M,K) row-major, B: (N,K) row-major, C: (M,N) row-major.
// Block 128x128, BK=32, 512 threads, 16 warps of 32x32 warp tiles.
#define GBK 32
#define SPAD 8
#define SLD (GBK + SPAD)   // 40 bf16 per row

template<int ACT>
__global__ __launch_bounds__(512) void gemm_bf16(
    const float* __restrict__ A, const float* __restrict__ B,
    const float* __restrict__ bias, float* __restrict__ C,
    int M, int N, int K)
{
    __shared__ __nv_bfloat16 Ah[128][SLD], Al[128][SLD];
    __shared__ __nv_bfloat16 Bh[128][SLD], Bl[128][SLD];
    const int tid = threadIdx.x;
    const int lane = tid & 31, warp = tid >> 5;
    const int lr = lane >> 2, lc = lane & 3;
    const int wm = warp >> 2, wn = warp & 3;        // 4x4 warps
    const int bx = blockIdx.x, by = blockIdx.y;
    const float* Ab = A + (size_t)by * 128 * K;
    const float* Bb = B + (size_t)bx * 128 * K;

    float acc[2][4][4];
#pragma unroll
    for (int i = 0; i < 2; i++)
#pragma unroll
        for (int j = 0; j < 4; j++)
#pragma unroll
            for (int r = 0; r < 4; r++) acc[i][j][r] = 0.0f;

    for (int kt = 0; kt < K; kt += GBK) {
#pragma unroll
        for (int i = 0; i < 2; i++) {
            int f = tid + i * 512;          // 1024 float4s per tile
            int row = f >> 3, c4 = (f & 7) * 4;
            float4 va = *(const float4*)(Ab + (size_t)row * K + kt + c4);
            float h0,l0,h1,l1,h2,l2,h3,l3;
            hilo(va.x,h0,l0); hilo(va.y,h1,l1); hilo(va.z,h2,l2); hilo(va.w,h3,l3);
            *(uint32_t*)&Ah[row][c4]   = packbf(h0,h1);
            *(uint32_t*)&Ah[row][c4+2] = packbf(h2,h3);
            *(uint32_t*)&Al[row][c4]   = packbf(l0,l1);
            *(uint32_t*)&Al[row][c4+2] = packbf(l2,l3);
            float4 vb = *(const float4*)(Bb + (size_t)row * K + kt + c4);
            hilo(vb.x,h0,l0); hilo(vb.y,h1,l1); hilo(vb.z,h2,l2); hilo(vb.w,h3,l3);
            *(uint32_t*)&Bh[row][c4]   = packbf(h0,h1);
            *(uint32_t*)&Bh[row][c4+2] = packbf(h2,h3);
            *(uint32_t*)&Bl[row][c4]   = packbf(l0,l1);
            *(uint32_t*)&Bl[row][c4+2] = packbf(l2,l3);
        }
        __syncthreads();
#pragma unroll
        for (int ks = 0; ks < GBK; ks += 16) {
            uint32_t ah[2][4], al_[2][4], bh[4][2], bl[4][2];
#pragma unroll
            for (int i = 0; i < 2; i++) {
                int r0 = wm * 32 + i * 16 + lr;
                ah[i][0]  = *(uint32_t*)&Ah[r0    ][ks + 2*lc];
                ah[i][1]  = *(uint32_t*)&Ah[r0 + 8][ks + 2*lc];
                ah[i][2]  = *(uint32_t*)&Ah[r0    ][ks + 8 + 2*lc];
                ah[i][3]  = *(uint32_t*)&Ah[r0 + 8][ks + 8 + 2*lc];
                al_[i][0] = *(uint32_t*)&Al[r0    ][ks + 2*lc];
                al_[i][1] = *(uint32_t*)&Al[r0 + 8][ks + 2*lc];
                al_[i][2] = *(uint32_t*)&Al[r0    ][ks + 8 + 2*lc];
                al_[i][3] = *(uint32_t*)&Al[r0 + 8][ks + 8 + 2*lc];
            }
#pragma unroll
            for (int j = 0; j < 4; j++) {
                int n0 = wn * 32 + j * 8 + lr;
                bh[j][0] = *(uint32_t*)&Bh[n0][ks + 2*lc];
                bh[j][1] = *(uint32_t*)&Bh[n0][ks + 8 + 2*lc];
                bl[j][0] = *(uint32_t*)&Bl[n0][ks + 2*lc];
                bl[j][1] = *(uint32_t*)&Bl[n0][ks + 8 + 2*lc];
            }
#pragma unroll
            for (int i = 0; i < 2; i++)
#pragma unroll
                for (int j = 0; j < 4; j++) {
                    mma_bf16(acc[i][j], ah[i][0],ah[i][1],ah[i][2],ah[i][3], bh[j][0],bh[j][1]);
                    mma_bf16(acc[i][j], ah[i][0],ah[i][1],ah[i][2],ah[i][3], bl[j][0],bl[j][1]);
                    mma_bf16(acc[i][j], al_[i][0],al_[i][1],al_[i][2],al_[i][3], bh[j][0],bh[j][1]);
                }
        }
        __syncthreads();
    }

    // epilogue
#pragma unroll
    for (int i = 0; i < 2; i++) {
        int row0 = by * 128 + wm * 32 + i * 16 + lr;
#pragma unroll
        for (int j = 0; j < 4; j++) {
            int col = bx * 128 + wn * 32 + j * 8 + 2 * lc;
            float b0 = bias ? bias[col]     : 0.0f;
            float b1 = bias ? bias[col + 1] : 0.0f;
            float v[4];
            v[0] = acc[i][j][0] + b0; v[1] = acc[i][j][1] + b1;
            v[2] = acc[i][j][2] + b0; v[3] = acc[i][j][3] + b1;
#pragma unroll
            for (int r = 0; r < 4; r++) {
                float xx = v[r];
                if (ACT == 1) xx = xx > 0.0f ? xx : 0.2f * xx;
                else if (ACT == 2) xx = 0.5f * xx * (1.0f + erff(xx * 0.70710678118654752f));
                v[r] = xx;
            }
            *(float2*)(C + (size_t)row0 * N + col)       = make_float2(v[0], v[1]);
            *(float2*)(C + (size_t)(row0 + 8) * N + col) = make_float2(v[2], v[3]);
        }
    }
}

// ---------------- tensor-core flash attention ---------------------------------
// grid (N/128, H, B), 256 threads (8 warps x 16 qrows). Key tile = 64.
// Q hi/lo frags in regs, K hi/lo in smem, V hi/lo transposed in smem.
// QK^T and P.V both use 2-way bf16 split (3 MMA products each).
#define KPAD 8
#define KLD (64 + KPAD)   // 72

__global__ __launch_bounds__(256) void attn_mma(
    const float* __restrict__ Q, const float* __restrict__ K,
    const float* __restrict__ V, float* __restrict__ O,
    int ldq, int ldkv)
{
    __shared__ __nv_bfloat16 Kh[64][KLD], Kl[64][KLD];
    __shared__ __nv_bfloat16 Vth[64][KLD], Vtl[64][KLD];
    const int b = blockIdx.z, h = blockIdx.y, qt = blockIdx.x;
    const int tid = threadIdx.x;
    const int lane = tid & 31, warp = tid >> 5;
    const int lr = lane >> 2, lc = lane & 3;

    const float* Qp = Q + ((size_t)b * NTOK + qt * 128 + warp * 16) * ldq + h * 64;
    const float* Kp = K + ((size_t)b * NTOK) * ldkv + h * 64;
    const float* Vp = V + ((size_t)b * NTOK) * ldkv + h * 64;

    // Q fragments (hi/lo), 4 k-tiles over 64 dims
    uint32_t qh[4][4], ql[4][4];
#pragma unroll
    for (int kk = 0; kk < 4; kk++) {
        float2 v00 = *(const float2*)(Qp + (size_t)lr * ldq + kk * 16 + 2 * lc);
        float2 v10 = *(const float2*)(Qp + (size_t)(lr + 8) * ldq + kk * 16 + 2 * lc);
        float2 v01 = *(const float2*)(Qp + (size_t)lr * ldq + kk * 16 + 8 + 2 * lc);
        float2 v11 = *(const float2*)(Qp + (size_t)(lr + 8) * ldq + kk * 16 + 8 + 2 * lc);
        float h0,l0,h1,l1;
        hilo(v00.x,h0,l0); hilo(v00.y,h1,l1); qh[kk][0]=packbf(h0,h1); ql[kk][0]=packbf(l0,l1);
        hilo(v10.x,h0,l0); hilo(v10.y,h1,l1); qh[kk][1]=packbf(h0,h1); ql[kk][1]=packbf(l0,l1);
        hilo(v01.x,h0,l0); hilo(v01.y,h1,l1); qh[kk][2]=packbf(h0,h1); ql[kk][2]=packbf(l0,l1);
        hilo(v11.x,h0,l0); hilo(v11.y,h1,l1); qh[kk][3]=packbf(h0,h1); ql[kk][3]=packbf(l0,l1);
    }

    float m0 = -1e30f, m1 = -1e30f, l0s = 0.0f, l1s = 0.0f;
    float o[8][4];
#pragma unroll
    for (int j = 0; j < 8; j++)
#pragma unroll
        for (int r = 0; r < 4; r++) o[j][r] = 0.0f;

    for (int kt = 0; kt < NTOK / 64; kt++) {
        __syncthreads();
#pragma unroll
        for (int i = 0; i < 4; i++) {
            int f = tid + i * 256;             // 1024 float4s
            int row = f >> 4, c4 = (f & 15) * 4;
            float4 kv = *(const float4*)(Kp + (size_t)(kt * 64 + row) * ldkv + c4);
            float h0,lo0,h1,lo1,h2,lo2,h3,lo3;
            hilo(kv.x,h0,lo0); hilo(kv.y,h1,lo1); hilo(kv.z,h2,lo2); hilo(kv.w,h3,lo3);
            *(uint32_t*)&Kh[row][c4]   = packbf(h0,h1);
            *(uint32_t*)&Kh[row][c4+2] = packbf(h2,h3);
            *(uint32_t*)&Kl[row][c4]   = packbf(lo0,lo1);
            *(uint32_t*)&Kl[row][c4+2] = packbf(lo2,lo3);
            float4 vv = *(const float4*)(Vp + (size_t)(kt * 64 + row) * ldkv + c4);
            hilo(vv.x,h0,lo0); hilo(vv.y,h1,lo1); hilo(vv.z,h2,lo2); hilo(vv.w,h3,lo3);
            Vth[c4+0][row] = __float2bfloat16_rn(h0);
            Vth[c4+1][row] = __float2bfloat16_rn(h1);
            Vth[c4+2][row] = __float2bfloat16_rn(h2);
            Vth[c4+3][row] = __float2bfloat16_rn(h3);
            Vtl[c4+0][row] = __float2bfloat16_rn(lo0);
            Vtl[c4+1][row] = __float2bfloat16_rn(lo1);
            Vtl[c4+2][row] = __float2bfloat16_rn(lo2);
            Vtl[c4+3][row] = __float2bfloat16_rn(lo3);
        }
        __syncthreads();

        // S = Q K^T (hi/lo split on both operands, 3 products)
        float s[8][4];
#pragma unroll
        for (int j = 0; j < 8; j++)
#pragma unroll
            for (int r = 0; r < 4; r++) s[j][r] = 0.0f;
#pragma unroll
        for (int j = 0; j < 8; j++) {
            int n0 = j * 8 + lr;
#pragma unroll
            for (int kk = 0; kk < 4; kk++) {
                uint32_t b0h = *(uint32_t*)&Kh[n0][kk*16 + 2*lc];
                uint32_t b1h = *(uint32_t*)&Kh[n0][kk*16 + 8 + 2*lc];
                uint32_t b0l = *(uint32_t*)&Kl[n0][kk*16 + 2*lc];
                uint32_t b1l = *(uint32_t*)&Kl[n0][kk*16 + 8 + 2*lc];
                mma_bf16(s[j], qh[kk][0],qh[kk][1],qh[kk][2],qh[kk][3], b0h, b1h);
                mma_bf16(s[j], qh[kk][0],qh[kk][1],qh[kk][2],qh[kk][3], b0l, b1l);
                mma_bf16(s[j], ql[kk][0],ql[kk][1],ql[kk][2],ql[kk][3], b0h, b1h);
            }
        }

        // softmax (online), rows r0=lr, r1=lr+8 shared by 4-lane groups
        float tmax0 = -1e30f, tmax1 = -1e30f;
#pragma unroll
        for (int j = 0; j < 8; j++) {
            s[j][0] *= 0.125f; s[j][1] *= 0.125f; s[j][2] *= 0.125f; s[j][3] *= 0.125f;
            tmax0 = fmaxf(tmax0, fmaxf(s[j][0], s[j][1]));
            tmax1 = fmaxf(tmax1, fmaxf(s[j][2], s[j][3]));
        }
        tmax0 = fmaxf(tmax0, __shfl_xor_sync(0xffffffffu, tmax0, 1));
        tmax0 = fmaxf(tmax0, __shfl_xor_sync(0xffffffffu, tmax0, 2));
        tmax1 = fmaxf(tmax1, __shfl_xor_sync(0xffffffffu, tmax1, 1));
        tmax1 = fmaxf(tmax1, __shfl_xor_sync(0xffffffffu, tmax1, 2));
        float mn0 = fmaxf(m0, tmax0), mn1 = fmaxf(m1, tmax1);
        float a0 = __expf(m0 - mn0),  a1 = __expf(m1 - mn1);
        m0 = mn0; m1 = mn1;
        float sum0 = 0.0f, sum1 = 0.0f;
#pragma unroll
        for (int j = 0; j < 8; j++) {
            s[j][0] = __expf(s[j][0] - m0); s[j][1] = __expf(s[j][1] - m0);
            s[j][2] = __expf(s[j][2] - m1); s[j][3] = __expf(s[j][3] - m1);
            sum0 += s[j][0] + s[j][1];
            sum1 += s[j][2] + s[j][3];
        }
        sum0 += __shfl_xor_sync(0xffffffffu, sum0, 1);
        sum0 += __shfl_xor_sync(0xffffffffu, sum0, 2);
        sum1 += __shfl_xor_sync(0xffffffffu, sum1, 1);
        sum1 += __shfl_xor_sync(0xffffffffu, sum1, 2);
        l0s = l0s * a0 + sum0;
        l1s = l1s * a1 + sum1;
#pragma unroll
        for (int j = 0; j < 8; j++) {
            o[j][0] *= a0; o[j][1] *= a0; o[j][2] *= a1; o[j][3] *= a1;
        }

        // O += P @ V  (P hi/lo from regs, V hi/lo from smem: 3 products)
#pragma unroll
        for (int kk = 0; kk < 4; kk++) {
            float h00,l00,h01,l01,h10,l10,h11,l11;
            float h20,l20,h21,l21,h30,l30,h31,l31;
            hilo(s[2*kk][0],  h00,l00); hilo(s[2*kk][1],  h01,l01);
            hilo(s[2*kk][2],  h10,l10); hilo(s[2*kk][3],  h11,l11);
            hilo(s[2*kk+1][0],h20,l20); hilo(s[2*kk+1][1],h21,l21);
            hilo(s[2*kk+1][2],h30,l30); hilo(s[2*kk+1][3],h31,l31);
            uint32_t pah0 = packbf(h00,h01), pal0 = packbf(l00,l01);
            uint32_t pah1 = packbf(h10,h11), pal1 = packbf(l10,l11);
            uint32_t pah2 = packbf(h20,h21), pal2 = packbf(l20,l21);
            uint32_t pah3 = packbf(h30,h31), pal3 = packbf(l30,l31);
#pragma unroll
            for (int j = 0; j < 8; j++) {
                int n0 = j * 8 + lr;
                uint32_t b0h = *(uint32_t*)&Vth[n0][kk*16 + 2*lc];
                uint32_t b1h = *(uint32_t*)&Vth[n0][kk*16 + 8 + 2*lc];
                uint32_t b0l = *(uint32_t*)&Vtl[n0][kk*16 + 2*lc];
                uint32_t b1l = *(uint32_t*)&Vtl[n0][kk*16 + 8 + 2*lc];
                mma_bf16(o[j], pah0, pah1, pah2, pah3, b0h, b1h);
                mma_bf16(o[j], pah0, pah1, pah2, pah3, b0l, b1l);
                mma_bf16(o[j], pal0, pal1, pal2, pal3, b0h, b1h);
            }
        }
    }

    float inv0 = 1.0f / l0s, inv1 = 1.0f / l1s;
    float* Op = O + ((size_t)b * NTOK + qt * 128 + warp * 16) * IDIM + h * 64;
#pragma unroll
    for (int j = 0; j < 8; j++) {
        int col = j * 8 + 2 * lc;
        *(float2*)(Op + (size_t)lr * IDIM + col)       = make_float2(o[j][0]*inv0, o[j][1]*inv0);
        *(float2*)(Op + (size_t)(lr + 8) * IDIM + col) = make_float2(o[j][2]*inv1, o[j][3]*inv1);
    }
}

// ---------------- Column L2-norm over the token axis ---------------------------
__global__ __launch_bounds__(256) void colnorm_ck_kernel(
    const float* __restrict__ src, float* __restrict__ dst)
{
    const int hh = blockIdx.x, b = blockIdx.y;
    __shared__ float red[256];
    __shared__ float inv[64];
    const int tid = threadIdx.x;
    const int d = tid & 63;
    const int ng = tid >> 6;
    const float* s = src + (((size_t)b * CHh + hh) * NTOK) * CDd;
    float acc = 0.0f;
    for (int n = ng; n < NTOK; n += 4) {
        float v = s[(size_t)n * CDd + d];
        acc += v * v;
    }
    red[tid] = acc;
    __syncthreads();
    if (tid < 64) {
        float t = red[tid] + red[tid+64] + red[tid+128] + red[tid+192];
        inv[tid] = 1.0f / fmaxf(sqrtf(t), 1e-12f);
    }
    __syncthreads();
    float iv = inv[d];
    float* dp = dst + (size_t)b * NTOK * CKDIM + hh * CDd;
    for (int n = ng; n < NTOK; n += 4) {
        dp[(size_t)n * CKDIM + d] = s[(size_t)n * CDd + d] * iv;
    }
}

__global__ __launch_bounds__(256) void colnorm_tok_kernel(
    const float* __restrict__ src, float* __restrict__ dst)
{
    const int hh = blockIdx.x, b = blockIdx.y;
    __shared__ float red[256];
    __shared__ float inv[64];
    const int tid = threadIdx.x;
    const int d = tid & 63;
    const int ng = tid >> 6;
    const float* s = src + (size_t)b * NTOK * IDIM + hh * 64;
    float acc = 0.0f;
    for (int n = ng; n < NTOK; n += 4) {
        float v = s[(size_t)n * IDIM + d];
        acc += v * v;
    }
    red[tid] = acc;
    __syncthreads();
    if (tid < 64) {
        float t = red[tid] + red[tid+64] + red[tid+128] + red[tid+192];
        inv[tid] = 1.0f / fmaxf(sqrtf(t), 1e-12f);
    }
    __syncthreads();
    float iv = inv[d];
    float* dp = dst + (size_t)b * NTOK * IDIM + hh * 64;
    for (int n = ng; n < NTOK; n += 4) {
        dp[(size_t)n * IDIM + d] = s[(size_t)n * IDIM + d] * iv;
    }
}

// ---------------- combine ------------------------------------------------------
__global__ __launch_bounds__(256) void combine_kernel(
    const float* __restrict__ a, const float* __restrict__ mlp,
    const float* __restrict__ ratio, float* __restrict__ dst)
{
    int i = blockIdx.x * blockDim.x + threadIdx.x;
    if (i < TOKENS * IDIM) {
        dst[i] = a[i] - mlp[i] * ratio[i & (IDIM - 1)];
    }
}

// ---------------- launch -------------------------------------------------------
extern "C" void kernel_launch(void* const* d_in, const int* in_sizes, int n_in,
                              void* d_out, int out_size)
{
    const float* x      = (const float*)d_in[0];
    const float* ck     = (const float*)d_in[1];
    const float* cv     = (const float*)d_in[2];
    const float* w_qkv  = (const float*)d_in[3];
    const float* w_out  = (const float*)d_in[4];
    const float* b_out  = (const float*)d_in[5];
    const float* ckw0   = (const float*)d_in[6];
    const float* ckb0   = (const float*)d_in[7];
    const float* ckw1   = (const float*)d_in[8];
    const float* ckb1   = (const float*)d_in[9];
    const float* ckw2   = (const float*)d_in[10];
    const float* ckb2   = (const float*)d_in[11];
    const float* cvw0   = (const float*)d_in[12];
    const float* cvb0   = (const float*)d_in[13];
    const float* cvw1   = (const float*)d_in[14];
    const float* cvb1   = (const float*)d_in[15];
    const float* cvw2   = (const float*)d_in[16];
    const float* cvb2   = (const float*)d_in[17];
    const float* nl_w   = (const float*)d_in[18];
    const float* nl_b   = (const float*)d_in[19];
    const float* ratio  = (const float*)d_in[20];
    float* out = (float*)d_out;

    float *qkv, *ckx, *ta, *tb, *ckh, *cvh, *oself, *octx, *mlp, *comb;
    cudaGetSymbolAddress((void**)&qkv,  g_qkv);
    cudaGetSymbolAddress((void**)&ckx,  g_ckx);
    cudaGetSymbolAddress((void**)&ta,   g_ta);
    cudaGetSymbolAddress((void**)&tb,   g_tb);
    cudaGetSymbolAddress((void**)&ckh,  g_ckh);
    cudaGetSymbolAddress((void**)&cvh,  g_cvh);
    cudaGetSymbolAddress((void**)&oself,g_out);
    cudaGetSymbolAddress((void**)&octx, g_outc);
    cudaGetSymbolAddress((void**)&mlp,  g_mlp);
    cudaGetSymbolAddress((void**)&comb, g_comb);

    dim3 gblk(512), ablk(256), eblk(256);

    // 1) qkv = x @ w_qkv^T
    gemm_bf16<0><<<dim3(3 * IDIM / 128, TOKENS / 128), gblk>>>(
        x, w_qkv, nullptr, qkv, TOKENS, 3 * IDIM, DMODEL);

    // 2) ck style vectorizer
    colnorm_ck_kernel<<<dim3(CHh, BATCH), eblk>>>(ck, ckx);
    gemm_bf16<1><<<dim3(IDIM / 128, TOKENS / 128), gblk>>>(ckx, ckw0, ckb0, ta, TOKENS, IDIM, CKDIM);
    gemm_bf16<1><<<dim3(IDIM / 128, TOKENS / 128), gblk>>>(ta,  ckw1, ckb1, tb, TOKENS, IDIM, IDIM);
    gemm_bf16<1><<<dim3(IDIM / 128, TOKENS / 128), gblk>>>(tb,  ckw2, ckb2, ckh, TOKENS, IDIM, IDIM);

    // 3) cv style vectorizer
    colnorm_ck_kernel<<<dim3(CHh, BATCH), eblk>>>(cv, ckx);
    gemm_bf16<1><<<dim3(IDIM / 128, TOKENS / 128), gblk>>>(ckx, cvw0, cvb0, ta, TOKENS, IDIM, CKDIM);
    gemm_bf16<1><<<dim3(IDIM / 128, TOKENS / 128), gblk>>>(ta,  cvw1, cvb1, tb, TOKENS, IDIM, IDIM);
    gemm_bf16<1><<<dim3(IDIM / 128, TOKENS / 128), gblk>>>(tb,  cvw2, cvb2, cvh, TOKENS, IDIM, IDIM);

    // 4) self attention (q|k|v column blocks of qkv, ld 1536)
    attn_mma<<<dim3(NTOK / 128, HEADS, BATCH), ablk>>>(
        qkv, qkv + IDIM, qkv + 2 * IDIM, oself, 3 * IDIM, 3 * IDIM);

    // 5) context attention
    attn_mma<<<dim3(NTOK / 128, HEADS, BATCH), ablk>>>(
        qkv, ckh, cvh, octx, 3 * IDIM, IDIM);

    // 6) MLP block
    colnorm_tok_kernel<<<dim3(IDIM / 64, BATCH), eblk>>>(octx, ta);
    gemm_bf16<2><<<dim3(IDIM / 128, TOKENS / 128), gblk>>>(ta, nl_w, nl_b, mlp, TOKENS, IDIM, IDIM);

    // 7) combine
    combine_kernel<<<(TOKENS * IDIM + 255) / 256, eblk>>>(oself, mlp, ratio, comb);

    // 8) final projection
    gemm_bf16<0><<<dim3(IDIM / 128, TOKENS / 128), gblk>>>(comb, w_out, b_out, out, TOKENS, IDIM, IDIM);
}

// round 4
// speedup vs baseline: 6.1677x; 1.3654x over previous
#include <cuda_runtime.h>
#include <cuda_bf16.h>
#include <math.h>
#include <stdint.h>

// Problem constants
#define BATCH 8
#define NTOK  1024
#define DMODEL 512
#define HEADS 8
#define DHEAD 64
#define CHh 6
#define CDd 64
#define IDIM 512
#define TOKENS (BATCH*NTOK)   // 8192
#define CKDIM (CHh*CDd)       // 384

// ---------------- scratch ----------------------------------------------------
__device__ float g_qkv [TOKENS * 3 * IDIM];
__device__ float g_ckx [TOKENS * CKDIM];
__device__ float g_ta  [TOKENS * IDIM];
__device__ float g_tb  [TOKENS * IDIM];
__device__ float g_ckh [TOKENS * IDIM];
__device__ float g_cvh [TOKENS * IDIM];
__device__ float g_out [TOKENS * IDIM];
__device__ float g_outc[TOKENS * IDIM];
__device__ float g_mlp [TOKENS * IDIM];

// ---------------- helpers ----------------------------------------------------
__device__ __forceinline__ void mma_bf16(float c[4],
    uint32_t a0, uint32_t a1, uint32_t a2, uint32_t a3,
    uint32_t b0, uint32_t b1)
{
    asm volatile(
        "mma.sync.aligned.m16n8k16.row.col.f32.bf16.bf16.f32 "
        "{%0,%1,%2,%3}, {%4,%5,%6,%7}, {%8,%9}, {%0,%1,%2,%3};\n"
        : "+f"(c[0]), "+f"(c[1]), "+f"(c[2]), "+f"(c[3])
        : "r"(a0), "r"(a1), "r"(a2), "r"(a3), "r"(b0), "r"(b1));
}

__device__ __forceinline__ void ldsm4(uint32_t& r0, uint32_t& r1, uint32_t& r2, uint32_t& r3,
                                      const void* p)
{
    uint32_t a = (uint32_t)__cvta_generic_to_shared(p);
    asm volatile("ldmatrix.sync.aligned.m8n8.x4.shared.b16 {%0,%1,%2,%3}, [%4];"
        : "=r"(r0), "=r"(r1), "=r"(r2), "=r"(r3) : "r"(a));
}
__device__ __forceinline__ void ldsm4t(uint32_t& r0, uint32_t& r1, uint32_t& r2, uint32_t& r3,
                                       const void* p)
{
    uint32_t a = (uint32_t)__cvta_generic_to_shared(p);
    asm volatile("ldmatrix.sync.aligned.m8n8.x4.trans.shared.b16 {%0,%1,%2,%3}, [%4];"
        : "=r"(r0), "=r"(r1), "=r"(r2), "=r"(r3) : "r"(a));
}

__device__ __forceinline__ uint32_t packbf(float x, float y) {
    __nv_bfloat162 t = __floats2bfloat162_rn(x, y);
    return *(uint32_t*)&t;
}
__device__ __forceinline__ void hilo(float x, float& h, float& l) {
    __nv_bfloat16 hb = __float2bfloat16_rn(x);
    h = __bfloat162float(hb);
    l = x - h;
}

// ---------------- bf16-split GEMM: C = act(A @ B^T + bias) ---------------------
// Block 128x128, BK=32, 512 threads, 16 warps (4x4) of 32x32 warp tiles.
// Double-buffered dynamic smem (80KB), ldmatrix fragment loads.
#define GBK 32
#define SLD 40                 // 32 + 8 pad (bf16 elems per row)
#define GT (128 * SLD)         // elems per stage per array

template<int ACT, int FUSE>
__global__ __launch_bounds__(512) void gemm_bf16(
    const float* __restrict__ A, const float* __restrict__ B,
    const float* __restrict__ bias, float* __restrict__ C,
    int M, int N, int K,
    const float* __restrict__ sub, const float* __restrict__ ratio)
{
    extern __shared__ __align__(16) __nv_bfloat16 smg[];
    __nv_bfloat16* Ah = smg;            // [2][GT]
    __nv_bfloat16* Al = smg + 2 * GT;
    __nv_bfloat16* Bh = smg + 4 * GT;
    __nv_bfloat16* Bl = smg + 6 * GT;

    const int tid = threadIdx.x;
    const int lane = tid & 31, warp = tid >> 5;
    const int lr = lane >> 2, lc = lane & 3;
    const int wm = warp >> 2, wn = warp & 3;
    const int bx = blockIdx.x, by = blockIdx.y;
    const float* Ab = A + (size_t)by * 128 * K;
    const float* Sb = FUSE ? (sub + (size_t)by * 128 * K) : nullptr;
    const float* Bb = B + (size_t)bx * 128 * K;

    // loader indices: 1024 float4 per 128x32 tile, 2 per thread
    int lrow[2], lcol[2];
#pragma unroll
    for (int i = 0; i < 2; i++) {
        int f = tid + i * 512;
        lrow[i] = f >> 3;
        lcol[i] = (f & 7) * 4;
    }
    // ldmatrix per-lane source coords
    const int a_r = wm * 32 + (lane & 15);
    const int a_c = (lane >> 4) * 8;
    const int b_r = wn * 32 + (lane & 7) + ((lane & 16) ? 8 : 0);
    const int b_c = (lane & 8) ? 8 : 0;

    float acc[2][4][4];
#pragma unroll
    for (int i = 0; i < 2; i++)
#pragma unroll
        for (int j = 0; j < 4; j++)
#pragma unroll
            for (int r = 0; r < 4; r++) acc[i][j][r] = 0.0f;

    float4 pa[2], pb[2];

    // prefetch tile 0
#pragma unroll
    for (int i = 0; i < 2; i++) {
        pa[i] = *(const float4*)(Ab + (size_t)lrow[i] * K + lcol[i]);
        if (FUSE) {
            float4 sb = *(const float4*)(Sb + (size_t)lrow[i] * K + lcol[i]);
            float4 rr = *(const float4*)(ratio + lcol[i]);
            pa[i].x -= sb.x * rr.x; pa[i].y -= sb.y * rr.y;
            pa[i].z -= sb.z * rr.z; pa[i].w -= sb.w * rr.w;
        }
        pb[i] = *(const float4*)(Bb + (size_t)lrow[i] * K + lcol[i]);
    }
    // store stage 0
#pragma unroll
    for (int i = 0; i < 2; i++) {
        float h0,l0,h1,l1,h2,l2,h3,l3;
        int off = lrow[i] * SLD + lcol[i];
        hilo(pa[i].x,h0,l0); hilo(pa[i].y,h1,l1); hilo(pa[i].z,h2,l2); hilo(pa[i].w,h3,l3);
        *(uint32_t*)&Ah[off]   = packbf(h0,h1); *(uint32_t*)&Ah[off+2] = packbf(h2,h3);
        *(uint32_t*)&Al[off]   = packbf(l0,l1); *(uint32_t*)&Al[off+2] = packbf(l2,l3);
        hilo(pb[i].x,h0,l0); hilo(pb[i].y,h1,l1); hilo(pb[i].z,h2,l2); hilo(pb[i].w,h3,l3);
        *(uint32_t*)&Bh[off]   = packbf(h0,h1); *(uint32_t*)&Bh[off+2] = packbf(h2,h3);
        *(uint32_t*)&Bl[off]   = packbf(l0,l1); *(uint32_t*)&Bl[off+2] = packbf(l2,l3);
    }
    __syncthreads();

    const int ktiles = K / GBK;
    for (int kt = 0; kt < ktiles; kt++) {
        const int cur = kt & 1;
        const bool has_next = (kt + 1 < ktiles);
        if (has_next) {
            int kg = (kt + 1) * GBK;
#pragma unroll
            for (int i = 0; i < 2; i++) {
                pa[i] = *(const float4*)(Ab + (size_t)lrow[i] * K + kg + lcol[i]);
                if (FUSE) {
                    float4 sb = *(const float4*)(Sb + (size_t)lrow[i] * K + kg + lcol[i]);
                    float4 rr = *(const float4*)(ratio + kg + lcol[i]);
                    pa[i].x -= sb.x * rr.x; pa[i].y -= sb.y * rr.y;
                    pa[i].z -= sb.z * rr.z; pa[i].w -= sb.w * rr.w;
                }
                pb[i] = *(const float4*)(Bb + (size_t)lrow[i] * K + kg + lcol[i]);
            }
        }

        const __nv_bfloat16* Ah_s = Ah + cur * GT;
        const __nv_bfloat16* Al_s = Al + cur * GT;
        const __nv_bfloat16* Bh_s = Bh + cur * GT;
        const __nv_bfloat16* Bl_s = Bl + cur * GT;
#pragma unroll
        for (int ks = 0; ks < GBK; ks += 16) {
            uint32_t ah[2][4], al_[2][4], bh[4][2], bl[4][2];
#pragma unroll
            for (int i = 0; i < 2; i++) {
                ldsm4(ah[i][0], ah[i][1], ah[i][2], ah[i][3],
                      Ah_s + (a_r + i * 16) * SLD + a_c + ks);
                ldsm4(al_[i][0], al_[i][1], al_[i][2], al_[i][3],
                      Al_s + (a_r + i * 16) * SLD + a_c + ks);
            }
#pragma unroll
            for (int jp = 0; jp < 2; jp++) {
                ldsm4(bh[2*jp][0], bh[2*jp][1], bh[2*jp+1][0], bh[2*jp+1][1],
                      Bh_s + (b_r + jp * 16) * SLD + b_c + ks);
                ldsm4(bl[2*jp][0], bl[2*jp][1], bl[2*jp+1][0], bl[2*jp+1][1],
                      Bl_s + (b_r + jp * 16) * SLD + b_c + ks);
            }
#pragma unroll
            for (int i = 0; i < 2; i++)
#pragma unroll
                for (int j = 0; j < 4; j++) {
                    mma_bf16(acc[i][j], ah[i][0],ah[i][1],ah[i][2],ah[i][3], bh[j][0],bh[j][1]);
                    mma_bf16(acc[i][j], ah[i][0],ah[i][1],ah[i][2],ah[i][3], bl[j][0],bl[j][1]);
                    mma_bf16(acc[i][j], al_[i][0],al_[i][1],al_[i][2],al_[i][3], bh[j][0],bh[j][1]);
                }
        }

        if (has_next) {
            const int nxt = (kt + 1) & 1;
            __nv_bfloat16* Ah_n = Ah + nxt * GT;
            __nv_bfloat16* Al_n = Al + nxt * GT;
            __nv_bfloat16* Bh_n = Bh + nxt * GT;
            __nv_bfloat16* Bl_n = Bl + nxt * GT;
#pragma unroll
            for (int i = 0; i < 2; i++) {
                float h0,l0,h1,l1,h2,l2,h3,l3;
                int off = lrow[i] * SLD + lcol[i];
                hilo(pa[i].x,h0,l0); hilo(pa[i].y,h1,l1); hilo(pa[i].z,h2,l2); hilo(pa[i].w,h3,l3);
                *(uint32_t*)&Ah_n[off]   = packbf(h0,h1); *(uint32_t*)&Ah_n[off+2] = packbf(h2,h3);
                *(uint32_t*)&Al_n[off]   = packbf(l0,l1); *(uint32_t*)&Al_n[off+2] = packbf(l2,l3);
                hilo(pb[i].x,h0,l0); hilo(pb[i].y,h1,l1); hilo(pb[i].z,h2,l2); hilo(pb[i].w,h3,l3);
                *(uint32_t*)&Bh_n[off]   = packbf(h0,h1); *(uint32_t*)&Bh_n[off+2] = packbf(h2,h3);
                *(uint32_t*)&Bl_n[off]   = packbf(l0,l1); *(uint32_t*)&Bl_n[off+2] = packbf(l2,l3);
            }
            __syncthreads();
        }
    }

    // epilogue
#pragma unroll
    for (int i = 0; i < 2; i++) {
        int row0 = by * 128 + wm * 32 + i * 16 + lr;
#pragma unroll
        for (int j = 0; j < 4; j++) {
            int col = bx * 128 + wn * 32 + j * 8 + 2 * lc;
            float b0 = bias ? bias[col]     : 0.0f;
            float b1 = bias ? bias[col + 1] : 0.0f;
            float v[4];
            v[0] = acc[i][j][0] + b0; v[1] = acc[i][j][1] + b1;
            v[2] = acc[i][j][2] + b0; v[3] = acc[i][j][3] + b1;
#pragma unroll
            for (int r = 0; r < 4; r++) {
                float xx = v[r];
                if (ACT == 1) xx = xx > 0.0f ? xx : 0.2f * xx;
                else if (ACT == 2) xx = 0.5f * xx * (1.0f + erff(xx * 0.70710678118654752f));
                v[r] = xx;
            }
            *(float2*)(C + (size_t)row0 * N + col)       = make_float2(v[0], v[1]);
            *(float2*)(C + (size_t)(row0 + 8) * N + col) = make_float2(v[2], v[3]);
        }
    }
}

// ---------------- tensor-core flash attention ---------------------------------
// grid (N/128, H, B), 256 threads (8 warps x 16 qrows). Key tile = 64.
// K and V both stored natural [key][dim] hi/lo; K frags via ldmatrix,
// V frags via ldmatrix.trans. Register prefetch of next K/V tile.
#define KLD 72   // 64 + 8 pad

__global__ __launch_bounds__(256) void attn_mma(
    const float* __restrict__ Q, const float* __restrict__ K,
    const float* __restrict__ V, float* __restrict__ O,
    int ldq, int ldkv)
{
    __shared__ __nv_bfloat16 Kh[64][KLD], Kl[64][KLD];
    __shared__ __nv_bfloat16 Vh[64][KLD], Vl[64][KLD];
    const int b = blockIdx.z, h = blockIdx.y, qt = blockIdx.x;
    const int tid = threadIdx.x;
    const int lane = tid & 31, warp = tid >> 5;
    const int lr = lane >> 2, lc = lane & 3;

    const float* Qp = Q + ((size_t)b * NTOK + qt * 128 + warp * 16) * ldq + h * 64;
    const float* Kp = K + ((size_t)b * NTOK) * ldkv + h * 64;
    const float* Vp = V + ((size_t)b * NTOK) * ldkv + h * 64;

    // Q fragments (hi/lo), 4 k-tiles over 64 dims
    uint32_t qh[4][4], ql[4][4];
#pragma unroll
    for (int kk = 0; kk < 4; kk++) {
        float2 v00 = *(const float2*)(Qp + (size_t)lr * ldq + kk * 16 + 2 * lc);
        float2 v10 = *(const float2*)(Qp + (size_t)(lr + 8) * ldq + kk * 16 + 2 * lc);
        float2 v01 = *(const float2*)(Qp + (size_t)lr * ldq + kk * 16 + 8 + 2 * lc);
        float2 v11 = *(const float2*)(Qp + (size_t)(lr + 8) * ldq + kk * 16 + 8 + 2 * lc);
        float h0,l0,h1,l1;
        hilo(v00.x,h0,l0); hilo(v00.y,h1,l1); qh[kk][0]=packbf(h0,h1); ql[kk][0]=packbf(l0,l1);
        hilo(v10.x,h0,l0); hilo(v10.y,h1,l1); qh[kk][1]=packbf(h0,h1); ql[kk][1]=packbf(l0,l1);
        hilo(v01.x,h0,l0); hilo(v01.y,h1,l1); qh[kk][2]=packbf(h0,h1); ql[kk][2]=packbf(l0,l1);
        hilo(v11.x,h0,l0); hilo(v11.y,h1,l1); qh[kk][3]=packbf(h0,h1); ql[kk][3]=packbf(l0,l1);
    }

    // loader coords (1024 float4 per 64x64 tile, 4 per thread)
    int prow[4], pcol[4];
#pragma unroll
    for (int i = 0; i < 4; i++) {
        int f = tid + i * 256;
        prow[i] = f >> 4;
        pcol[i] = (f & 15) * 4;
    }
    // ldmatrix coords
    const int k_r = (lane & 7) + ((lane & 16) ? 8 : 0);   // + jp*16
    const int k_c = (lane & 8) ? 8 : 0;                   // + kk*16
    const int v_r = (lane & 7) + ((lane & 8) ? 8 : 0);    // + kk*16
    const int v_c = (lane & 16) ? 8 : 0;                  // + jp*16

    float m0 = -1e30f, m1 = -1e30f, l0s = 0.0f, l1s = 0.0f;
    float o[8][4];
#pragma unroll
    for (int j = 0; j < 8; j++)
#pragma unroll
        for (int r = 0; r < 4; r++) o[j][r] = 0.0f;

    float4 pk[4], pv[4];
#pragma unroll
    for (int i = 0; i < 4; i++) {
        pk[i] = *(const float4*)(Kp + (size_t)prow[i] * ldkv + pcol[i]);
        pv[i] = *(const float4*)(Vp + (size_t)prow[i] * ldkv + pcol[i]);
    }

    for (int kt = 0; kt < NTOK / 64; kt++) {
        __syncthreads();
#pragma unroll
        for (int i = 0; i < 4; i++) {
            float h0,lo0,h1,lo1,h2,lo2,h3,lo3;
            hilo(pk[i].x,h0,lo0); hilo(pk[i].y,h1,lo1); hilo(pk[i].z,h2,lo2); hilo(pk[i].w,h3,lo3);
            *(uint32_t*)&Kh[prow[i]][pcol[i]]   = packbf(h0,h1);
            *(uint32_t*)&Kh[prow[i]][pcol[i]+2] = packbf(h2,h3);
            *(uint32_t*)&Kl[prow[i]][pcol[i]]   = packbf(lo0,lo1);
            *(uint32_t*)&Kl[prow[i]][pcol[i]+2] = packbf(lo2,lo3);
            hilo(pv[i].x,h0,lo0); hilo(pv[i].y,h1,lo1); hilo(pv[i].z,h2,lo2); hilo(pv[i].w,h3,lo3);
            *(uint32_t*)&Vh[prow[i]][pcol[i]]   = packbf(h0,h1);
            *(uint32_t*)&Vh[prow[i]][pcol[i]+2] = packbf(h2,h3);
            *(uint32_t*)&Vl[prow[i]][pcol[i]]   = packbf(lo0,lo1);
            *(uint32_t*)&Vl[prow[i]][pcol[i]+2] = packbf(lo2,lo3);
        }
        __syncthreads();

        if (kt + 1 < NTOK / 64) {
            const float* Kn = Kp + (size_t)(kt + 1) * 64 * ldkv;
            const float* Vn = Vp + (size_t)(kt + 1) * 64 * ldkv;
#pragma unroll
            for (int i = 0; i < 4; i++) {
                pk[i] = *(const float4*)(Kn + (size_t)prow[i] * ldkv + pcol[i]);
                pv[i] = *(const float4*)(Vn + (size_t)prow[i] * ldkv + pcol[i]);
            }
        }

        // S = Q K^T (hi/lo split, 3 products), K frags via ldmatrix
        float s[8][4];
#pragma unroll
        for (int j = 0; j < 8; j++)
#pragma unroll
            for (int r = 0; r < 4; r++) s[j][r] = 0.0f;
#pragma unroll
        for (int kk = 0; kk < 4; kk++) {
#pragma unroll
            for (int jp = 0; jp < 4; jp++) {
                uint32_t kb0,kb1,kb2,kb3, lb0,lb1,lb2,lb3;
                ldsm4(kb0,kb1,kb2,kb3, &Kh[jp*16 + k_r][kk*16 + k_c]);
                ldsm4(lb0,lb1,lb2,lb3, &Kl[jp*16 + k_r][kk*16 + k_c]);
                mma_bf16(s[2*jp],   qh[kk][0],qh[kk][1],qh[kk][2],qh[kk][3], kb0, kb1);
                mma_bf16(s[2*jp],   qh[kk][0],qh[kk][1],qh[kk][2],qh[kk][3], lb0, lb1);
                mma_bf16(s[2*jp],   ql[kk][0],ql[kk][1],ql[kk][2],ql[kk][3], kb0, kb1);
                mma_bf16(s[2*jp+1], qh[kk][0],qh[kk][1],qh[kk][2],qh[kk][3], kb2, kb3);
                mma_bf16(s[2*jp+1], qh[kk][0],qh[kk][1],qh[kk][2],qh[kk][3], lb2, lb3);
                mma_bf16(s[2*jp+1], ql[kk][0],ql[kk][1],ql[kk][2],ql[kk][3], kb2, kb3);
            }
        }

        // online softmax
        float tmax0 = -1e30f, tmax1 = -1e30f;
#pragma unroll
        for (int j = 0; j < 8; j++) {
            s[j][0] *= 0.125f; s[j][1] *= 0.125f; s[j][2] *= 0.125f; s[j][3] *= 0.125f;
            tmax0 = fmaxf(tmax0, fmaxf(s[j][0], s[j][1]));
            tmax1 = fmaxf(tmax1, fmaxf(s[j][2], s[j][3]));
        }
        tmax0 = fmaxf(tmax0, __shfl_xor_sync(0xffffffffu, tmax0, 1));
        tmax0 = fmaxf(tmax0, __shfl_xor_sync(0xffffffffu, tmax0, 2));
        tmax1 = fmaxf(tmax1, __shfl_xor_sync(0xffffffffu, tmax1, 1));
        tmax1 = fmaxf(tmax1, __shfl_xor_sync(0xffffffffu, tmax1, 2));
        float mn0 = fmaxf(m0, tmax0), mn1 = fmaxf(m1, tmax1);
        float a0 = __expf(m0 - mn0),  a1 = __expf(m1 - mn1);
        m0 = mn0; m1 = mn1;
        float sum0 = 0.0f, sum1 = 0.0f;
#pragma unroll
        for (int j = 0; j < 8; j++) {
            s[j][0] = __expf(s[j][0] - m0); s[j][1] = __expf(s[j][1] - m0);
            s[j][2] = __expf(s[j][2] - m1); s[j][3] = __expf(s[j][3] - m1);
            sum0 += s[j][0] + s[j][1];
            sum1 += s[j][2] + s[j][3];
        }
        sum0 += __shfl_xor_sync(0xffffffffu, sum0, 1);
        sum0 += __shfl_xor_sync(0xffffffffu, sum0, 2);
        sum1 += __shfl_xor_sync(0xffffffffu, sum1, 1);
        sum1 += __shfl_xor_sync(0xffffffffu, sum1, 2);
        l0s = l0s * a0 + sum0;
        l1s = l1s * a1 + sum1;
#pragma unroll
        for (int j = 0; j < 8; j++) {
            o[j][0] *= a0; o[j][1] *= a0; o[j][2] *= a1; o[j][3] *= a1;
        }

        // O += P @ V (hi/lo split both sides, V frags via ldmatrix.trans)
#pragma unroll
        for (int kk = 0; kk < 4; kk++) {
            float h00,l00,h01,l01,h10,l10,h11,l11;
            float h20,l20,h21,l21,h30,l30,h31,l31;
            hilo(s[2*kk][0],  h00,l00); hilo(s[2*kk][1],  h01,l01);
            hilo(s[2*kk][2],  h10,l10); hilo(s[2*kk][3],  h11,l11);
            hilo(s[2*kk+1][0],h20,l20); hilo(s[2*kk+1][1],h21,l21);
            hilo(s[2*kk+1][2],h30,l30); hilo(s[2*kk+1][3],h31,l31);
            uint32_t pah0 = packbf(h00,h01), pal0 = packbf(l00,l01);
            uint32_t pah1 = packbf(h10,h11), pal1 = packbf(l10,l11);
            uint32_t pah2 = packbf(h20,h21), pal2 = packbf(l20,l21);
            uint32_t pah3 = packbf(h30,h31), pal3 = packbf(l30,l31);
#pragma unroll
            for (int jp = 0; jp < 4; jp++) {
                uint32_t vb0,vb1,vb2,vb3, wb0,wb1,wb2,wb3;
                ldsm4t(vb0,vb1,vb2,vb3, &Vh[kk*16 + v_r][jp*16 + v_c]);
                ldsm4t(wb0,wb1,wb2,wb3, &Vl[kk*16 + v_r][jp*16 + v_c]);
                mma_bf16(o[2*jp],   pah0,pah1,pah2,pah3, vb0, vb1);
                mma_bf16(o[2*jp],   pah0,pah1,pah2,pah3, wb0, wb1);
                mma_bf16(o[2*jp],   pal0,pal1,pal2,pal3, vb0, vb1);
                mma_bf16(o[2*jp+1], pah0,pah1,pah2,pah3, vb2, vb3);
                mma_bf16(o[2*jp+1], pah0,pah1,pah2,pah3, wb2, wb3);
                mma_bf16(o[2*jp+1], pal0,pal1,pal2,pal3, vb2, vb3);
            }
        }
    }

    float inv0 = 1.0f / l0s, inv1 = 1.0f / l1s;
    float* Op = O + ((size_t)b * NTOK + qt * 128 + warp * 16) * IDIM + h * 64;
#pragma unroll
    for (int j = 0; j < 8; j++) {
        int col = j * 8 + 2 * lc;
        *(float2*)(Op + (size_t)lr * IDIM + col)       = make_float2(o[j][0]*inv0, o[j][1]*inv0);
        *(float2*)(Op + (size_t)(lr + 8) * IDIM + col) = make_float2(o[j][2]*inv1, o[j][3]*inv1);
    }
}

// ---------------- Column L2-norm over the token axis ---------------------------
__global__ __launch_bounds__(256) void colnorm_ck_kernel(
    const float* __restrict__ src, float* __restrict__ dst)
{
    const int hh = blockIdx.x, b = blockIdx.y;
    __shared__ float red[256];
    __shared__ float inv[64];
    const int tid = threadIdx.x;
    const int d = tid & 63;
    const int ng = tid >> 6;
    const float* s = src + (((size_t)b * CHh + hh) * NTOK) * CDd;
    float acc = 0.0f;
    for (int n = ng; n < NTOK; n += 4) {
        float v = s[(size_t)n * CDd + d];
        acc += v * v;
    }
    red[tid] = acc;
    __syncthreads();
    if (tid < 64) {
        float t = red[tid] + red[tid+64] + red[tid+128] + red[tid+192];
        inv[tid] = 1.0f / fmaxf(sqrtf(t), 1e-12f);
    }
    __syncthreads();
    float iv = inv[d];
    float* dp = dst + (size_t)b * NTOK * CKDIM + hh * CDd;
    for (int n = ng; n < NTOK; n += 4) {
        dp[(size_t)n * CKDIM + d] = s[(size_t)n * CDd + d] * iv;
    }
}

__global__ __launch_bounds__(256) void colnorm_tok_kernel(
    const float* __restrict__ src, float* __restrict__ dst)
{
    const int hh = blockIdx.x, b = blockIdx.y;
    __shared__ float red[256];
    __shared__ float inv[64];
    const int tid = threadIdx.x;
    const int d = tid & 63;
    const int ng = tid >> 6;
    const float* s = src + (size_t)b * NTOK * IDIM + hh * 64;
    float acc = 0.0f;
    for (int n = ng; n < NTOK; n += 4) {
        float v = s[(size_t)n * IDIM + d];
        acc += v * v;
    }
    red[tid] = acc;
    __syncthreads();
    if (tid < 64) {
        float t = red[tid] + red[tid+64] + red[tid+128] + red[tid+192];
        inv[tid] = 1.0f / fmaxf(sqrtf(t), 1e-12f);
    }
    __syncthreads();
    float iv = inv[d];
    float* dp = dst + (size_t)b * NTOK * IDIM + hh * 64;
    for (int n = ng; n < NTOK; n += 4) {
        dp[(size_t)n * IDIM + d] = s[(size_t)n * IDIM + d] * iv;
    }
}

// ---------------- launch -------------------------------------------------------
#define GEMM_SMEM (8 * GT * 2)   // bytes: 8 arrays-halves * GT elems * 2B = 81920

extern "C" void kernel_launch(void* const* d_in, const int* in_sizes, int n_in,
                              void* d_out, int out_size)
{
    const float* x      = (const float*)d_in[0];
    const float* ck     = (const float*)d_in[1];
    const float* cv     = (const float*)d_in[2];
    const float* w_qkv  = (const float*)d_in[3];
    const float* w_out  = (const float*)d_in[4];
    const float* b_out  = (const float*)d_in[5];
    const float* ckw0   = (const float*)d_in[6];
    const float* ckb0   = (const float*)d_in[7];
    const float* ckw1   = (const float*)d_in[8];
    const float* ckb1   = (const float*)d_in[9];
    const float* ckw2   = (const float*)d_in[10];
    const float* ckb2   = (const float*)d_in[11];
    const float* cvw0   = (const float*)d_in[12];
    const float* cvb0   = (const float*)d_in[13];
    const float* cvw1   = (const float*)d_in[14];
    const float* cvb1   = (const float*)d_in[15];
    const float* cvw2   = (const float*)d_in[16];
    const float* cvb2   = (const float*)d_in[17];
    const float* nl_w   = (const float*)d_in[18];
    const float* nl_b   = (const float*)d_in[19];
    const float* ratio  = (const float*)d_in[20];
    float* out = (float*)d_out;

    float *qkv, *ckx, *ta, *tb, *ckh, *cvh, *oself, *octx, *mlp;
    cudaGetSymbolAddress((void**)&qkv,  g_qkv);
    cudaGetSymbolAddress((void**)&ckx,  g_ckx);
    cudaGetSymbolAddress((void**)&ta,   g_ta);
    cudaGetSymbolAddress((void**)&tb,   g_tb);
    cudaGetSymbolAddress((void**)&ckh,  g_ckh);
    cudaGetSymbolAddress((void**)&cvh,  g_cvh);
    cudaGetSymbolAddress((void**)&oself,g_out);
    cudaGetSymbolAddress((void**)&octx, g_outc);
    cudaGetSymbolAddress((void**)&mlp,  g_mlp);

    static bool attr_set = false;
    if (!attr_set) {
        cudaFuncSetAttribute(gemm_bf16<0,0>, cudaFuncAttributeMaxDynamicSharedMemorySize, GEMM_SMEM);
        cudaFuncSetAttribute(gemm_bf16<1,0>, cudaFuncAttributeMaxDynamicSharedMemorySize, GEMM_SMEM);
        cudaFuncSetAttribute(gemm_bf16<2,0>, cudaFuncAttributeMaxDynamicSharedMemorySize, GEMM_SMEM);
        cudaFuncSetAttribute(gemm_bf16<0,1>, cudaFuncAttributeMaxDynamicSharedMemorySize, GEMM_SMEM);
        attr_set = true;
    }

    dim3 gblk(512), ablk(256), eblk(256);

    // 1) qkv = x @ w_qkv^T
    gemm_bf16<0,0><<<dim3(3 * IDIM / 128, TOKENS / 128), gblk, GEMM_SMEM>>>(
        x, w_qkv, nullptr, qkv, TOKENS, 3 * IDIM, DMODEL, nullptr, nullptr);

    // 2) ck style vectorizer
    colnorm_ck_kernel<<<dim3(CHh, BATCH), eblk>>>(ck, ckx);
    gemm_bf16<1,0><<<dim3(IDIM / 128, TOKENS / 128), gblk, GEMM_SMEM>>>(
        ckx, ckw0, ckb0, ta, TOKENS, IDIM, CKDIM, nullptr, nullptr);
    gemm_bf16<1,0><<<dim3(IDIM / 128, TOKENS / 128), gblk, GEMM_SMEM>>>(
        ta,  ckw1, ckb1, tb, TOKENS, IDIM, IDIM, nullptr, nullptr);
    gemm_bf16<1,0><<<dim3(IDIM / 128, TOKENS / 128), gblk, GEMM_SMEM>>>(
        tb,  ckw2, ckb2, ckh, TOKENS, IDIM, IDIM, nullptr, nullptr);

    // 3) cv style vectorizer
    colnorm_ck_kernel<<<dim3(CHh, BATCH), eblk>>>(cv, ckx);
    gemm_bf16<1,0><<<dim3(IDIM / 128, TOKENS / 128), gblk, GEMM_SMEM>>>(
        ckx, cvw0, cvb0, ta, TOKENS, IDIM, CKDIM, nullptr, nullptr);
    gemm_bf16<1,0><<<dim3(IDIM / 128, TOKENS / 128), gblk, GEMM_SMEM>>>(
        ta,  cvw1, cvb1, tb, TOKENS, IDIM, IDIM, nullptr, nullptr);
    gemm_bf16<1,0><<<dim3(IDIM / 128, TOKENS / 128), gblk, GEMM_SMEM>>>(
        tb,  cvw2, cvb2, cvh, TOKENS, IDIM, IDIM, nullptr, nullptr);

    // 4) self attention
    attn_mma<<<dim3(NTOK / 128, HEADS, BATCH), ablk>>>(
        qkv, qkv + IDIM, qkv + 2 * IDIM, oself, 3 * IDIM, 3 * IDIM);

    // 5) context attention
    attn_mma<<<dim3(NTOK / 128, HEADS, BATCH), ablk>>>(
        qkv, ckh, cvh, octx, 3 * IDIM, IDIM);

    // 6) MLP block
    colnorm_tok_kernel<<<dim3(IDIM / 64, BATCH), eblk>>>(octx, ta);
    gemm_bf16<2,0><<<dim3(IDIM / 128, TOKENS / 128), gblk, GEMM_SMEM>>>(
        ta, nl_w, nl_b, mlp, TOKENS, IDIM, IDIM, nullptr, nullptr);

    // 7+8) fused combine + final projection: out = (oself - mlp*ratio) @ w_out^T + b_out
    gemm_bf16<0,1><<<dim3(IDIM / 128, TOKENS / 128), gblk, GEMM_SMEM>>>(
        oself, w_out, b_out, out, TOKENS, IDIM, IDIM, mlp, ratio);
}